// round 1
// baseline (speedup 1.0000x reference)
#include <cuda_runtime.h>
#include <cuda_bf16.h>
#include <math.h>

#define N_NODES 50000
#define N_EDGES 400000
#define HDIM 64
#define EDIM 8
#define MHID 128
#define RHID 128
#define TE 32   // edges per block in message kernel

// Scratch (device globals: no allocation allowed)
__device__ float g_h[N_NODES * HDIM];
__device__ float g_agg[N_NODES * HDIM];

__global__ void init_kernel(const float* __restrict__ nf) {
    int i = blockIdx.x * blockDim.x + threadIdx.x;
    if (i < N_NODES * HDIM) { g_h[i] = nf[i]; g_agg[i] = 0.f; }
}

__global__ void zero_agg_kernel() {
    int i = blockIdx.x * blockDim.x + threadIdx.x;
    if (i < N_NODES * HDIM) g_agg[i] = 0.f;
}

// ---------------------------------------------------------------------------
// Message kernel: per block, 32 edges.
//   x[e] = concat(h[src[e]], h[dst[e]], ef[e])  (136)
//   hidden = relu(x @ W1 + b1)                  (128)
//   m = hidden @ W2 + b2                        (64)
//   atomicAdd into g_agg[dst[e]]
// 256 threads: GEMM1 micro-tile 2 edges x 8 cols, GEMM2 2 edges x 4 cols.
// ---------------------------------------------------------------------------
__global__ __launch_bounds__(256) void msg_kernel(
    const float* __restrict__ ef,
    const int* __restrict__ src, const int* __restrict__ dst,
    const float* __restrict__ W1, const float* __restrict__ b1,
    const float* __restrict__ W2, const float* __restrict__ b2)
{
    __shared__ float xs[TE][136];
    __shared__ float hs[TE][132];
    __shared__ int   sdst[TE];

    const int e0  = blockIdx.x * TE;
    const int tid = threadIdx.x;

    if (tid < TE) sdst[tid] = dst[e0 + tid];

    // Stage gathered inputs: coalesced 64-wide row reads of h.
    for (int i = tid; i < TE * 64; i += 256) {
        int e = i >> 6, c = i & 63;
        int s = src[e0 + e];
        int d = dst[e0 + e];
        xs[e][c]      = g_h[(long)s * HDIM + c];
        xs[e][64 + c] = g_h[(long)d * HDIM + c];
    }
    {
        int e = tid >> 3, c = tid & 7;           // 256 threads = 32 edges x 8
        xs[e][128 + c] = ef[(long)(e0 + e) * EDIM + c];
    }
    __syncthreads();

    // --- GEMM1: [32 x 136] @ [136 x 128] -> relu -> hs ---
    const int er = tid >> 4;   // 0..15 -> edges 2er, 2er+1 (same across warp quarter)
    const int hc = tid & 15;   // 0..15 -> cols 8hc..8hc+7  (coalesced W reads)

    float acc0[8], acc1[8];
    {
        const float4* bp = reinterpret_cast<const float4*>(b1 + hc * 8);
        float4 bA = bp[0], bB = bp[1];
        acc0[0]=bA.x; acc0[1]=bA.y; acc0[2]=bA.z; acc0[3]=bA.w;
        acc0[4]=bB.x; acc0[5]=bB.y; acc0[6]=bB.z; acc0[7]=bB.w;
        #pragma unroll
        for (int j = 0; j < 8; j++) acc1[j] = acc0[j];
    }

    #pragma unroll 8
    for (int k = 0; k < 136; k++) {
        float a0 = xs[2*er][k];
        float a1 = xs[2*er+1][k];
        const float4* wp = reinterpret_cast<const float4*>(W1 + (long)k * MHID + hc * 8);
        float4 wA = wp[0], wB = wp[1];
        acc0[0] = fmaf(a0, wA.x, acc0[0]); acc1[0] = fmaf(a1, wA.x, acc1[0]);
        acc0[1] = fmaf(a0, wA.y, acc0[1]); acc1[1] = fmaf(a1, wA.y, acc1[1]);
        acc0[2] = fmaf(a0, wA.z, acc0[2]); acc1[2] = fmaf(a1, wA.z, acc1[2]);
        acc0[3] = fmaf(a0, wA.w, acc0[3]); acc1[3] = fmaf(a1, wA.w, acc1[3]);
        acc0[4] = fmaf(a0, wB.x, acc0[4]); acc1[4] = fmaf(a1, wB.x, acc1[4]);
        acc0[5] = fmaf(a0, wB.y, acc0[5]); acc1[5] = fmaf(a1, wB.y, acc1[5]);
        acc0[6] = fmaf(a0, wB.z, acc0[6]); acc1[6] = fmaf(a1, wB.z, acc1[6]);
        acc0[7] = fmaf(a0, wB.w, acc0[7]); acc1[7] = fmaf(a1, wB.w, acc1[7]);
    }
    #pragma unroll
    for (int j = 0; j < 8; j++) {
        hs[2*er][hc*8 + j]   = fmaxf(acc0[j], 0.f);
        hs[2*er+1][hc*8 + j] = fmaxf(acc1[j], 0.f);
    }
    __syncthreads();

    // --- GEMM2: [32 x 128] @ [128 x 64] + b2 -> scatter ---
    const int oc = tid & 15;   // cols 4oc..4oc+3
    float m0[4], m1[4];
    {
        float4 bv = *reinterpret_cast<const float4*>(b2 + oc * 4);
        m0[0]=bv.x; m0[1]=bv.y; m0[2]=bv.z; m0[3]=bv.w;
        #pragma unroll
        for (int j = 0; j < 4; j++) m1[j] = m0[j];
    }
    #pragma unroll 8
    for (int k = 0; k < 128; k++) {
        float a0 = hs[2*er][k];
        float a1 = hs[2*er+1][k];
        float4 w = *reinterpret_cast<const float4*>(W2 + (long)k * HDIM + oc * 4);
        m0[0] = fmaf(a0, w.x, m0[0]); m1[0] = fmaf(a1, w.x, m1[0]);
        m0[1] = fmaf(a0, w.y, m0[1]); m1[1] = fmaf(a1, w.y, m1[1]);
        m0[2] = fmaf(a0, w.z, m0[2]); m1[2] = fmaf(a1, w.z, m1[2]);
        m0[3] = fmaf(a0, w.w, m0[3]); m1[3] = fmaf(a1, w.w, m1[3]);
    }
    long d0 = sdst[2*er], d1 = sdst[2*er+1];
    #pragma unroll
    for (int j = 0; j < 4; j++) {
        atomicAdd(&g_agg[d0 * HDIM + oc*4 + j], m0[j]);
        atomicAdd(&g_agg[d1 * HDIM + oc*4 + j], m1[j]);
    }
}

// ---------------------------------------------------------------------------
// GRU update: one warp handles 4 nodes (W reuse x4).
// gates layout along 192 cols: [z | r | hcand]; lane owns cols lane+32j, j=0..5
// ---------------------------------------------------------------------------
__device__ __forceinline__ float sigmoidf(float x) { return 1.f / (1.f + expf(-x)); }

__global__ __launch_bounds__(256) void gru_kernel(
    const float* __restrict__ Wx, const float* __restrict__ Wh,
    const float* __restrict__ bg)
{
    __shared__ float sx[8][4][64];
    __shared__ float sh[8][4][64];
    const int w    = threadIdx.x >> 5;
    const int lane = threadIdx.x & 31;
    const long wg  = (long)blockIdx.x * 8 + w;
    const long n0  = wg * 4;

    for (int idx = lane; idx < 256; idx += 32) {
        int n = idx >> 6, c = idx & 63;
        long node = n0 + n;
        if (node < N_NODES) {
            sx[w][n][c] = g_agg[node * HDIM + c];
            sh[w][n][c] = g_h[node * HDIM + c];
        }
    }
    __syncwarp();
    if (n0 >= N_NODES) return;   // warp-uniform

    float gx[6][4], gh[6][4];
    #pragma unroll
    for (int j = 0; j < 6; j++) {
        float b = bg[lane + 32*j];
        #pragma unroll
        for (int n = 0; n < 4; n++) { gx[j][n] = b; gh[j][n] = 0.f; }
    }

    #pragma unroll 4
    for (int k = 0; k < 64; k++) {
        float wxv[6], whv[6];
        #pragma unroll
        for (int j = 0; j < 6; j++) {
            wxv[j] = Wx[(long)k * 192 + lane + 32*j];
            whv[j] = Wh[(long)k * 192 + lane + 32*j];
        }
        #pragma unroll
        for (int n = 0; n < 4; n++) {
            float xk = sx[w][n][k];
            float hk = sh[w][n][k];
            #pragma unroll
            for (int j = 0; j < 6; j++) {
                gx[j][n] = fmaf(xk, wxv[j], gx[j][n]);
                gh[j][n] = fmaf(hk, whv[j], gh[j][n]);
            }
        }
    }

    #pragma unroll
    for (int n = 0; n < 4; n++) {
        long node = n0 + n;
        #pragma unroll
        for (int half = 0; half < 2; half++) {
            float z  = sigmoidf(gx[half][n]   + gh[half][n]);
            float r  = sigmoidf(gx[2+half][n] + gh[2+half][n]);
            float hc = tanhf(gx[4+half][n] + r * gh[4+half][n]);
            float hv = sh[w][n][lane + 32*half];
            g_h[node * HDIM + lane + 32*half] = z * hv + (1.f - z) * hc;
        }
    }
}

// ---------------------------------------------------------------------------
// Readout: relu(h @ Wr1 + br1) @ Wr2 + br2. One warp per 4 nodes.
// ---------------------------------------------------------------------------
__global__ __launch_bounds__(256) void readout_kernel(
    const float* __restrict__ W1, const float* __restrict__ b1,
    const float* __restrict__ W2, const float* __restrict__ b2,
    float* __restrict__ out)
{
    __shared__ float sh[8][4][64];
    const int w    = threadIdx.x >> 5;
    const int lane = threadIdx.x & 31;
    const long wg  = (long)blockIdx.x * 8 + w;
    const long n0  = wg * 4;

    for (int idx = lane; idx < 256; idx += 32) {
        int n = idx >> 6, c = idx & 63;
        long node = n0 + n;
        if (node < N_NODES) sh[w][n][c] = g_h[node * HDIM + c];
    }
    __syncwarp();
    if (n0 >= N_NODES) return;

    float acc[4][4];
    #pragma unroll
    for (int n = 0; n < 4; n++)
        #pragma unroll
        for (int j = 0; j < 4; j++) acc[n][j] = 0.f;

    #pragma unroll 4
    for (int k = 0; k < 64; k++) {
        float wv[4];
        #pragma unroll
        for (int j = 0; j < 4; j++) wv[j] = W1[(long)k * RHID + lane + 32*j];
        #pragma unroll
        for (int n = 0; n < 4; n++) {
            float hk = sh[w][n][k];
            #pragma unroll
            for (int j = 0; j < 4; j++) acc[n][j] = fmaf(hk, wv[j], acc[n][j]);
        }
    }

    float bb1[4], w2v[4];
    #pragma unroll
    for (int j = 0; j < 4; j++) {
        bb1[j] = b1[lane + 32*j];
        w2v[j] = W2[lane + 32*j];
    }

    float part[4];
    #pragma unroll
    for (int n = 0; n < 4; n++) {
        float s = 0.f;
        #pragma unroll
        for (int j = 0; j < 4; j++) {
            float hv = fmaxf(acc[n][j] + bb1[j], 0.f);
            s = fmaf(hv, w2v[j], s);
        }
        part[n] = s;
    }
    #pragma unroll
    for (int off = 16; off; off >>= 1) {
        #pragma unroll
        for (int n = 0; n < 4; n++)
            part[n] += __shfl_xor_sync(0xffffffffu, part[n], off);
    }
    if (lane == 0) {
        float bb = b2[0];
        #pragma unroll
        for (int n = 0; n < 4; n++) out[n0 + n] = part[n] + bb;
    }
}

extern "C" void kernel_launch(void* const* d_in, const int* in_sizes, int n_in,
                              void* d_out, int out_size) {
    const float* nf  = (const float*)d_in[0];
    const float* ef  = (const float*)d_in[1];
    const int*   src = (const int*)  d_in[2];
    const int*   dst = (const int*)  d_in[3];
    const float* W1  = (const float*)d_in[4];
    const float* b1  = (const float*)d_in[5];
    const float* W2  = (const float*)d_in[6];
    const float* b2  = (const float*)d_in[7];
    const float* Wx  = (const float*)d_in[8];
    const float* Wh  = (const float*)d_in[9];
    const float* bg  = (const float*)d_in[10];
    const float* Wr1 = (const float*)d_in[11];
    const float* br1 = (const float*)d_in[12];
    const float* Wr2 = (const float*)d_in[13];
    const float* br2 = (const float*)d_in[14];
    float* out = (float*)d_out;

    const int nb_nh = (N_NODES * HDIM + 255) / 256;        // 12500
    const int nwarp = N_NODES / 4;                         // 12500 warps
    const int nwb   = (nwarp + 7) / 8;                     // 1563 blocks

    init_kernel<<<nb_nh, 256>>>(nf);
    for (int t = 0; t < 2; t++) {
        if (t) zero_agg_kernel<<<nb_nh, 256>>>();
        msg_kernel<<<N_EDGES / TE, 256>>>(ef, src, dst, W1, b1, W2, b2);
        gru_kernel<<<nwb, 256>>>(Wx, Wh, bg);
    }
    readout_kernel<<<nwb, 256>>>(Wr1, br1, Wr2, br2, out);
}

// round 2
// speedup vs baseline: 1.6248x; 1.6248x over previous
#include <cuda_runtime.h>
#include <cuda_bf16.h>
#include <math.h>

#define N_NODES 50000
#define N_EDGES 400000
#define HDIM 64
#define EDIM 8
#define MHID 128
#define RHID 128
#define TE 64    // edges per block in message kernel
#define PB 64    // nodes per block in projection kernel

// Scratch (device globals: no allocation allowed)
__device__ float g_h[N_NODES * HDIM];
__device__ float g_agg[N_NODES * HDIM];
__device__ float g_P[N_NODES * 2 * MHID];   // [node][256]: cols 0..127 = h@W1a, 128..255 = h@W1b

__global__ void init_kernel(const float* __restrict__ nf) {
    int i = blockIdx.x * blockDim.x + threadIdx.x;
    if (i < N_NODES * HDIM) { g_h[i] = nf[i]; g_agg[i] = 0.f; }
}

// ---------------------------------------------------------------------------
// Projection: P[n][0:128] = h[n] @ W1[0:64], P[n][128:256] = h[n] @ W1[64:128]
// 64 nodes / block, 256 threads. Thread = 8 nodes (stride 8) x 8 cols.
// ---------------------------------------------------------------------------
__global__ __launch_bounds__(256) void proj_kernel(const float* __restrict__ W1) {
    __shared__ float sh[PB][HDIM];
    const int n0  = blockIdx.x * PB;
    const int tid = threadIdx.x;

    for (int i = tid; i < PB * HDIM; i += 256) {
        int r = i >> 6, c = i & 63;
        int node = n0 + r;
        sh[r][c] = (node < N_NODES) ? g_h[(long)node * HDIM + c] : 0.f;
    }
    __syncthreads();

    const int hc = tid & 31;          // col group: output cols hc*8 .. hc*8+7 (of 256)
    const int nr = tid >> 5;          // node sub-index: nodes nr, nr+8, ..., nr+56
    const int j0 = hc * 8;
    // cols <128 come from W1 rows 0..63 (src part); cols >=128 from rows 64..127 (dst part)
    const float* Wbase = (j0 < 128) ? (W1 + j0) : (W1 + 64 * MHID + (j0 - 128));

    float acc[8][8];
    #pragma unroll
    for (int n = 0; n < 8; n++)
        #pragma unroll
        for (int j = 0; j < 8; j++) acc[n][j] = 0.f;

    #pragma unroll 2
    for (int k = 0; k < HDIM; k++) {
        const float4* wp = reinterpret_cast<const float4*>(Wbase + (long)k * MHID);
        float4 wA = wp[0], wB = wp[1];
        float w0 = wA.x, w1 = wA.y, w2 = wA.z, w3 = wA.w;
        float w4 = wB.x, w5 = wB.y, w6 = wB.z, w7 = wB.w;
        #pragma unroll
        for (int n = 0; n < 8; n++) {
            float a = sh[nr + 8 * n][k];
            acc[n][0] = fmaf(a, w0, acc[n][0]);
            acc[n][1] = fmaf(a, w1, acc[n][1]);
            acc[n][2] = fmaf(a, w2, acc[n][2]);
            acc[n][3] = fmaf(a, w3, acc[n][3]);
            acc[n][4] = fmaf(a, w4, acc[n][4]);
            acc[n][5] = fmaf(a, w5, acc[n][5]);
            acc[n][6] = fmaf(a, w6, acc[n][6]);
            acc[n][7] = fmaf(a, w7, acc[n][7]);
        }
    }

    #pragma unroll
    for (int n = 0; n < 8; n++) {
        int node = n0 + nr + 8 * n;
        if (node < N_NODES) {
            float4* op = reinterpret_cast<float4*>(g_P + (long)node * 256 + j0);
            op[0] = make_float4(acc[n][0], acc[n][1], acc[n][2], acc[n][3]);
            op[1] = make_float4(acc[n][4], acc[n][5], acc[n][6], acc[n][7]);
        }
    }
}

// ---------------------------------------------------------------------------
// Message kernel (64 edges/block, 256 threads):
//   hidden[e] = relu(P[src][0:128] + P[dst][128:256] + ef[e]@W1c + b1)
//   m[e]      = hidden[e] @ W2 + b2
//   red.v4 scatter into g_agg[dst]
// ---------------------------------------------------------------------------
__global__ __launch_bounds__(256) void msg_kernel(
    const float* __restrict__ ef,
    const int* __restrict__ src, const int* __restrict__ dst,
    const float* __restrict__ W1, const float* __restrict__ b1,
    const float* __restrict__ W2, const float* __restrict__ b2)
{
    __shared__ float hid[TE][132];       // padded stride
    __shared__ float sW1c[EDIM][MHID];   // W1 rows 128..135
    __shared__ float sb1[MHID];
    __shared__ float sb2[HDIM];
    __shared__ int   ssrc[TE], sdst[TE];
    __shared__ float sef[TE][EDIM];

    const int e0  = blockIdx.x * TE;
    const int tid = threadIdx.x;

    if (tid < TE) { ssrc[tid] = src[e0 + tid]; sdst[tid] = dst[e0 + tid]; }
    for (int i = tid; i < TE * EDIM; i += 256)
        sef[i >> 3][i & 7] = ef[(long)e0 * EDIM + i];
    for (int i = tid; i < EDIM * MHID; i += 256)
        sW1c[i >> 7][i & 127] = W1[128 * MHID + i];
    if (tid < MHID) sb1[tid] = b1[tid];
    if (tid < HDIM) sb2[tid] = b2[tid];
    __syncthreads();

    // Stage 2: hidden. Thread = 1 edge x 32 cols.
    {
        const int e  = tid >> 2;
        const int c0 = (tid & 3) * 32;
        const int s = ssrc[e], d = sdst[e];
        const float* ps = g_P + (long)s * 256 + c0;
        const float* pd = g_P + (long)d * 256 + 128 + c0;
        float efr[EDIM];
        #pragma unroll
        for (int k = 0; k < EDIM; k++) efr[k] = sef[e][k];

        #pragma unroll
        for (int j4 = 0; j4 < 8; j4++) {
            float4 a  = *reinterpret_cast<const float4*>(ps + j4 * 4);
            float4 bq = *reinterpret_cast<const float4*>(pd + j4 * 4);
            int c = c0 + j4 * 4;
            float v0 = a.x + bq.x + sb1[c + 0];
            float v1 = a.y + bq.y + sb1[c + 1];
            float v2 = a.z + bq.z + sb1[c + 2];
            float v3 = a.w + bq.w + sb1[c + 3];
            #pragma unroll
            for (int k = 0; k < EDIM; k++) {
                float e_k = efr[k];
                v0 = fmaf(e_k, sW1c[k][c + 0], v0);
                v1 = fmaf(e_k, sW1c[k][c + 1], v1);
                v2 = fmaf(e_k, sW1c[k][c + 2], v2);
                v3 = fmaf(e_k, sW1c[k][c + 3], v3);
            }
            hid[e][c + 0] = fmaxf(v0, 0.f);
            hid[e][c + 1] = fmaxf(v1, 0.f);
            hid[e][c + 2] = fmaxf(v2, 0.f);
            hid[e][c + 3] = fmaxf(v3, 0.f);
        }
    }
    __syncthreads();

    // Stage 3: GEMM2 [64x128]@[128x64]. Thread = 4 edges x 4 cols.
    const int er = tid >> 4;   // edges 4er..4er+3
    const int oc = tid & 15;   // cols oc*4..oc*4+3
    float m0[4], m1[4], m2[4], m3[4];
    {
        float b0 = sb2[oc * 4 + 0], b1v = sb2[oc * 4 + 1];
        float b2v = sb2[oc * 4 + 2], b3 = sb2[oc * 4 + 3];
        m0[0]=b0; m0[1]=b1v; m0[2]=b2v; m0[3]=b3;
        #pragma unroll
        for (int j = 0; j < 4; j++) { m1[j]=m0[j]; m2[j]=m0[j]; m3[j]=m0[j]; }
    }

    #pragma unroll 8
    for (int k = 0; k < MHID; k++) {
        float4 w = *reinterpret_cast<const float4*>(W2 + (long)k * HDIM + oc * 4);
        float a0 = hid[4*er + 0][k];
        float a1 = hid[4*er + 1][k];
        float a2 = hid[4*er + 2][k];
        float a3 = hid[4*er + 3][k];
        m0[0]=fmaf(a0,w.x,m0[0]); m0[1]=fmaf(a0,w.y,m0[1]); m0[2]=fmaf(a0,w.z,m0[2]); m0[3]=fmaf(a0,w.w,m0[3]);
        m1[0]=fmaf(a1,w.x,m1[0]); m1[1]=fmaf(a1,w.y,m1[1]); m1[2]=fmaf(a1,w.z,m1[2]); m1[3]=fmaf(a1,w.w,m1[3]);
        m2[0]=fmaf(a2,w.x,m2[0]); m2[1]=fmaf(a2,w.y,m2[1]); m2[2]=fmaf(a2,w.z,m2[2]); m2[3]=fmaf(a2,w.w,m2[3]);
        m3[0]=fmaf(a3,w.x,m3[0]); m3[1]=fmaf(a3,w.y,m3[1]); m3[2]=fmaf(a3,w.z,m3[2]); m3[3]=fmaf(a3,w.w,m3[3]);
    }

    #pragma unroll
    for (int i = 0; i < 4; i++) {
        long d = sdst[4*er + i];
        float* p = g_agg + d * HDIM + oc * 4;
        float* mv = (i == 0) ? m0 : (i == 1) ? m1 : (i == 2) ? m2 : m3;
        asm volatile("red.global.add.v4.f32 [%0], {%1, %2, %3, %4};"
                     :: "l"(p), "f"(mv[0]), "f"(mv[1]), "f"(mv[2]), "f"(mv[3])
                     : "memory");
    }
}

// ---------------------------------------------------------------------------
// GRU update (also zeroes g_agg after consuming it): one warp per 4 nodes.
// gates layout along 192 cols: [z | r | hcand]; lane owns cols lane+32j
// ---------------------------------------------------------------------------
__device__ __forceinline__ float sigmoidf(float x) { return 1.f / (1.f + expf(-x)); }

__global__ __launch_bounds__(256) void gru_kernel(
    const float* __restrict__ Wx, const float* __restrict__ Wh,
    const float* __restrict__ bg)
{
    __shared__ float sx[8][4][64];
    __shared__ float sh[8][4][64];
    const int w    = threadIdx.x >> 5;
    const int lane = threadIdx.x & 31;
    const long wg  = (long)blockIdx.x * 8 + w;
    const long n0  = wg * 4;

    for (int idx = lane; idx < 256; idx += 32) {
        int n = idx >> 6, c = idx & 63;
        long node = n0 + n;
        if (node < N_NODES) {
            sx[w][n][c] = g_agg[node * HDIM + c];
            g_agg[node * HDIM + c] = 0.f;       // ready for next step / next replay
            sh[w][n][c] = g_h[node * HDIM + c];
        }
    }
    __syncwarp();
    if (n0 >= N_NODES) return;   // warp-uniform

    float gx[6][4], gh[6][4];
    #pragma unroll
    for (int j = 0; j < 6; j++) {
        float b = bg[lane + 32*j];
        #pragma unroll
        for (int n = 0; n < 4; n++) { gx[j][n] = b; gh[j][n] = 0.f; }
    }

    #pragma unroll 4
    for (int k = 0; k < 64; k++) {
        float wxv[6], whv[6];
        #pragma unroll
        for (int j = 0; j < 6; j++) {
            wxv[j] = Wx[(long)k * 192 + lane + 32*j];
            whv[j] = Wh[(long)k * 192 + lane + 32*j];
        }
        #pragma unroll
        for (int n = 0; n < 4; n++) {
            float xk = sx[w][n][k];
            float hk = sh[w][n][k];
            #pragma unroll
            for (int j = 0; j < 6; j++) {
                gx[j][n] = fmaf(xk, wxv[j], gx[j][n]);
                gh[j][n] = fmaf(hk, whv[j], gh[j][n]);
            }
        }
    }

    #pragma unroll
    for (int n = 0; n < 4; n++) {
        long node = n0 + n;
        #pragma unroll
        for (int half = 0; half < 2; half++) {
            float z  = sigmoidf(gx[half][n]   + gh[half][n]);
            float r  = sigmoidf(gx[2+half][n] + gh[2+half][n]);
            float hc = tanhf(gx[4+half][n] + r * gh[4+half][n]);
            float hv = sh[w][n][lane + 32*half];
            g_h[node * HDIM + lane + 32*half] = z * hv + (1.f - z) * hc;
        }
    }
}

// ---------------------------------------------------------------------------
// Readout: relu(h @ Wr1 + br1) @ Wr2 + br2. One warp per 4 nodes.
// ---------------------------------------------------------------------------
__global__ __launch_bounds__(256) void readout_kernel(
    const float* __restrict__ W1, const float* __restrict__ b1,
    const float* __restrict__ W2, const float* __restrict__ b2,
    float* __restrict__ out)
{
    __shared__ float sh[8][4][64];
    const int w    = threadIdx.x >> 5;
    const int lane = threadIdx.x & 31;
    const long wg  = (long)blockIdx.x * 8 + w;
    const long n0  = wg * 4;

    for (int idx = lane; idx < 256; idx += 32) {
        int n = idx >> 6, c = idx & 63;
        long node = n0 + n;
        if (node < N_NODES) sh[w][n][c] = g_h[node * HDIM + c];
    }
    __syncwarp();
    if (n0 >= N_NODES) return;

    float acc[4][4];
    #pragma unroll
    for (int n = 0; n < 4; n++)
        #pragma unroll
        for (int j = 0; j < 4; j++) acc[n][j] = 0.f;

    #pragma unroll 4
    for (int k = 0; k < 64; k++) {
        float wv[4];
        #pragma unroll
        for (int j = 0; j < 4; j++) wv[j] = W1[(long)k * RHID + lane + 32*j];
        #pragma unroll
        for (int n = 0; n < 4; n++) {
            float hk = sh[w][n][k];
            #pragma unroll
            for (int j = 0; j < 4; j++) acc[n][j] = fmaf(hk, wv[j], acc[n][j]);
        }
    }

    float bb1[4], w2v[4];
    #pragma unroll
    for (int j = 0; j < 4; j++) {
        bb1[j] = b1[lane + 32*j];
        w2v[j] = W2[lane + 32*j];
    }

    float part[4];
    #pragma unroll
    for (int n = 0; n < 4; n++) {
        float s = 0.f;
        #pragma unroll
        for (int j = 0; j < 4; j++) {
            float hv = fmaxf(acc[n][j] + bb1[j], 0.f);
            s = fmaf(hv, w2v[j], s);
        }
        part[n] = s;
    }
    #pragma unroll
    for (int off = 16; off; off >>= 1) {
        #pragma unroll
        for (int n = 0; n < 4; n++)
            part[n] += __shfl_xor_sync(0xffffffffu, part[n], off);
    }
    if (lane == 0) {
        float bb = b2[0];
        #pragma unroll
        for (int n = 0; n < 4; n++) out[n0 + n] = part[n] + bb;
    }
}

extern "C" void kernel_launch(void* const* d_in, const int* in_sizes, int n_in,
                              void* d_out, int out_size) {
    const float* nf  = (const float*)d_in[0];
    const float* ef  = (const float*)d_in[1];
    const int*   src = (const int*)  d_in[2];
    const int*   dst = (const int*)  d_in[3];
    const float* W1  = (const float*)d_in[4];
    const float* b1  = (const float*)d_in[5];
    const float* W2  = (const float*)d_in[6];
    const float* b2  = (const float*)d_in[7];
    const float* Wx  = (const float*)d_in[8];
    const float* Wh  = (const float*)d_in[9];
    const float* bg  = (const float*)d_in[10];
    const float* Wr1 = (const float*)d_in[11];
    const float* br1 = (const float*)d_in[12];
    const float* Wr2 = (const float*)d_in[13];
    const float* br2 = (const float*)d_in[14];
    float* out = (float*)d_out;

    const int nb_nh = (N_NODES * HDIM + 255) / 256;        // 12500
    const int nproj = (N_NODES + PB - 1) / PB;             // 782
    const int nwarp = N_NODES / 4;                         // 12500 warps
    const int nwb   = (nwarp + 7) / 8;                     // 1563 blocks

    init_kernel<<<nb_nh, 256>>>(nf);
    for (int t = 0; t < 2; t++) {
        proj_kernel<<<nproj, 256>>>(W1);
        msg_kernel<<<N_EDGES / TE, 256>>>(ef, src, dst, W1, b1, W2, b2);
        gru_kernel<<<nwb, 256>>>(Wx, Wh, bg);
    }
    readout_kernel<<<nwb, 256>>>(Wr1, br1, Wr2, br2, out);
}

// round 3
// speedup vs baseline: 1.6892x; 1.0397x over previous
#include <cuda_runtime.h>
#include <cuda_bf16.h>
#include <math.h>

#define N_NODES 50000
#define N_EDGES 400000
#define HDIM 64
#define EDIM 8
#define MHID 128
#define RHID 128
#define TE 64    // edges per block in message kernel
#define PB 64    // nodes per block in projection kernel
#define GB 64    // nodes per block in fused GRU kernel

// Scratch (device globals: no allocation allowed)
__device__ float g_h[N_NODES * HDIM];
__device__ float g_agg[N_NODES * HDIM];
__device__ float g_P[N_NODES * 2 * MHID];   // [node][256]: 0..127 = h@W1a, 128..255 = h@W1b

__device__ __forceinline__ float sigmoidf(float x) { return 1.f / (1.f + expf(-x)); }

__global__ void init_kernel(const float* __restrict__ nf) {
    int i = blockIdx.x * blockDim.x + threadIdx.x;
    if (i < N_NODES * HDIM) { g_h[i] = nf[i]; g_agg[i] = 0.f; }
}

// ---------------------------------------------------------------------------
// Standalone projection (t=0 only): P[n] = h[n] @ [W1a | W1b]
// ---------------------------------------------------------------------------
__global__ __launch_bounds__(256) void proj_kernel(const float* __restrict__ W1) {
    __shared__ float sh[PB][HDIM];
    const int n0  = blockIdx.x * PB;
    const int tid = threadIdx.x;

    for (int i = tid; i < PB * HDIM; i += 256) {
        int r = i >> 6, c = i & 63;
        int node = n0 + r;
        sh[r][c] = (node < N_NODES) ? g_h[(long)node * HDIM + c] : 0.f;
    }
    __syncthreads();

    const int hc = tid & 31;
    const int nr = tid >> 5;
    const int j0 = hc * 8;
    const float* Wbase = (j0 < 128) ? (W1 + j0) : (W1 + 64 * MHID + (j0 - 128));

    float acc[8][8];
    #pragma unroll
    for (int n = 0; n < 8; n++)
        #pragma unroll
        for (int j = 0; j < 8; j++) acc[n][j] = 0.f;

    #pragma unroll 2
    for (int k = 0; k < HDIM; k++) {
        const float4* wp = reinterpret_cast<const float4*>(Wbase + (long)k * MHID);
        float4 wA = wp[0], wB = wp[1];
        #pragma unroll
        for (int n = 0; n < 8; n++) {
            float a = sh[nr + 8 * n][k];
            acc[n][0] = fmaf(a, wA.x, acc[n][0]);
            acc[n][1] = fmaf(a, wA.y, acc[n][1]);
            acc[n][2] = fmaf(a, wA.z, acc[n][2]);
            acc[n][3] = fmaf(a, wA.w, acc[n][3]);
            acc[n][4] = fmaf(a, wB.x, acc[n][4]);
            acc[n][5] = fmaf(a, wB.y, acc[n][5]);
            acc[n][6] = fmaf(a, wB.z, acc[n][6]);
            acc[n][7] = fmaf(a, wB.w, acc[n][7]);
        }
    }

    #pragma unroll
    for (int n = 0; n < 8; n++) {
        int node = n0 + nr + 8 * n;
        if (node < N_NODES) {
            float4* op = reinterpret_cast<float4*>(g_P + (long)node * 256 + j0);
            op[0] = make_float4(acc[n][0], acc[n][1], acc[n][2], acc[n][3]);
            op[1] = make_float4(acc[n][4], acc[n][5], acc[n][6], acc[n][7]);
        }
    }
}

// ---------------------------------------------------------------------------
// Message kernel (64 edges/block, 256 threads)
// ---------------------------------------------------------------------------
__global__ __launch_bounds__(256) void msg_kernel(
    const float* __restrict__ ef,
    const int* __restrict__ src, const int* __restrict__ dst,
    const float* __restrict__ W1, const float* __restrict__ b1,
    const float* __restrict__ W2, const float* __restrict__ b2)
{
    __shared__ float hid[TE][132];
    __shared__ float sW1c[EDIM][MHID];
    __shared__ float sb1[MHID];
    __shared__ float sb2[HDIM];
    __shared__ int   ssrc[TE], sdst[TE];
    __shared__ float sef[TE][EDIM];

    const int e0  = blockIdx.x * TE;
    const int tid = threadIdx.x;

    if (tid < TE) { ssrc[tid] = src[e0 + tid]; sdst[tid] = dst[e0 + tid]; }
    for (int i = tid; i < TE * EDIM; i += 256)
        sef[i >> 3][i & 7] = ef[(long)e0 * EDIM + i];
    for (int i = tid; i < EDIM * MHID; i += 256)
        sW1c[i >> 7][i & 127] = W1[128 * MHID + i];
    if (tid < MHID) sb1[tid] = b1[tid];
    if (tid < HDIM) sb2[tid] = b2[tid];
    __syncthreads();

    {
        const int e  = tid >> 2;
        const int c0 = (tid & 3) * 32;
        const int s = ssrc[e], d = sdst[e];
        const float* ps = g_P + (long)s * 256 + c0;
        const float* pd = g_P + (long)d * 256 + 128 + c0;
        float efr[EDIM];
        #pragma unroll
        for (int k = 0; k < EDIM; k++) efr[k] = sef[e][k];

        #pragma unroll
        for (int j4 = 0; j4 < 8; j4++) {
            float4 a  = *reinterpret_cast<const float4*>(ps + j4 * 4);
            float4 bq = *reinterpret_cast<const float4*>(pd + j4 * 4);
            int c = c0 + j4 * 4;
            float v0 = a.x + bq.x + sb1[c + 0];
            float v1 = a.y + bq.y + sb1[c + 1];
            float v2 = a.z + bq.z + sb1[c + 2];
            float v3 = a.w + bq.w + sb1[c + 3];
            #pragma unroll
            for (int k = 0; k < EDIM; k++) {
                float e_k = efr[k];
                v0 = fmaf(e_k, sW1c[k][c + 0], v0);
                v1 = fmaf(e_k, sW1c[k][c + 1], v1);
                v2 = fmaf(e_k, sW1c[k][c + 2], v2);
                v3 = fmaf(e_k, sW1c[k][c + 3], v3);
            }
            hid[e][c + 0] = fmaxf(v0, 0.f);
            hid[e][c + 1] = fmaxf(v1, 0.f);
            hid[e][c + 2] = fmaxf(v2, 0.f);
            hid[e][c + 3] = fmaxf(v3, 0.f);
        }
    }
    __syncthreads();

    const int er = tid >> 4;
    const int oc = tid & 15;
    float m0[4], m1[4], m2[4], m3[4];
    {
        m0[0]=sb2[oc*4+0]; m0[1]=sb2[oc*4+1]; m0[2]=sb2[oc*4+2]; m0[3]=sb2[oc*4+3];
        #pragma unroll
        for (int j = 0; j < 4; j++) { m1[j]=m0[j]; m2[j]=m0[j]; m3[j]=m0[j]; }
    }

    #pragma unroll 8
    for (int k = 0; k < MHID; k++) {
        float4 w = *reinterpret_cast<const float4*>(W2 + (long)k * HDIM + oc * 4);
        float a0 = hid[4*er + 0][k];
        float a1 = hid[4*er + 1][k];
        float a2 = hid[4*er + 2][k];
        float a3 = hid[4*er + 3][k];
        m0[0]=fmaf(a0,w.x,m0[0]); m0[1]=fmaf(a0,w.y,m0[1]); m0[2]=fmaf(a0,w.z,m0[2]); m0[3]=fmaf(a0,w.w,m0[3]);
        m1[0]=fmaf(a1,w.x,m1[0]); m1[1]=fmaf(a1,w.y,m1[1]); m1[2]=fmaf(a1,w.z,m1[2]); m1[3]=fmaf(a1,w.w,m1[3]);
        m2[0]=fmaf(a2,w.x,m2[0]); m2[1]=fmaf(a2,w.y,m2[1]); m2[2]=fmaf(a2,w.z,m2[2]); m2[3]=fmaf(a2,w.w,m2[3]);
        m3[0]=fmaf(a3,w.x,m3[0]); m3[1]=fmaf(a3,w.y,m3[1]); m3[2]=fmaf(a3,w.z,m3[2]); m3[3]=fmaf(a3,w.w,m3[3]);
    }

    #pragma unroll
    for (int i = 0; i < 4; i++) {
        long d = sdst[4*er + i];
        float* p = g_agg + d * HDIM + oc * 4;
        float* mv = (i == 0) ? m0 : (i == 1) ? m1 : (i == 2) ? m2 : m3;
        asm volatile("red.global.add.v4.f32 [%0], {%1, %2, %3, %4};"
                     :: "l"(p), "f"(mv[0]), "f"(mv[1]), "f"(mv[2]), "f"(mv[3])
                     : "memory");
    }
}

// ---------------------------------------------------------------------------
// Fused GRU (+ projection for next step, OR readout on the last step).
// 64 nodes / block, 256 threads. Gates as block GEMM:
//   [z|r] cols from combined [x|h] @ [Wx;Wh]; candidate x- and h-parts split.
// Warp w owns nodes {w, w+8, ..., w+56}; lane owns cols lane+32j.
// Also consumes-and-zeroes g_agg (graph-replay invariant).
// ---------------------------------------------------------------------------
__global__ __launch_bounds__(256) void gru_fused_kernel(
    const float* __restrict__ Wx, const float* __restrict__ Wh,
    const float* __restrict__ bg, const float* __restrict__ W1,
    const float* __restrict__ Wr1, const float* __restrict__ br1,
    const float* __restrict__ Wr2, const float* __restrict__ br2,
    float* __restrict__ out, int do_proj)
{
    __shared__ float sxh[GB][128];   // cols 0..63 = x(agg), 64..127 = h_old
    const int tid  = threadIdx.x;
    const int lane = tid & 31;
    const int wid  = tid >> 5;
    const int n0   = blockIdx.x * GB;

    for (int i = tid; i < GB * 64; i += 256) {
        int r = i >> 6, c = i & 63;
        int node = n0 + r;
        float xv = 0.f, hv = 0.f;
        if (node < N_NODES) {
            long off = (long)node * HDIM + c;
            xv = g_agg[off];
            g_agg[off] = 0.f;
            hv = g_h[off];
        }
        sxh[r][c]      = xv;
        sxh[r][64 + c] = hv;
    }
    __syncthreads();

    // --- gates GEMM ---
    float acc[8][4];    // z (j=0,1), r (j=2,3): combined x+h parts
    float accx[8][2];   // candidate, x-part (+bias)
    float acch[8][2];   // candidate, h-part
    {
        float bz0 = bg[lane],      bz1 = bg[lane + 32];
        float br0 = bg[lane + 64], brr = bg[lane + 96];
        float bc0 = bg[lane + 128], bc1 = bg[lane + 160];
        #pragma unroll
        for (int n = 0; n < 8; n++) {
            acc[n][0]=bz0; acc[n][1]=bz1; acc[n][2]=br0; acc[n][3]=brr;
            accx[n][0]=bc0; accx[n][1]=bc1; acch[n][0]=0.f; acch[n][1]=0.f;
        }
    }

    #pragma unroll 4
    for (int k = 0; k < 64; k++) {           // x @ Wx
        const float* wr = Wx + (long)k * 192;
        float w0=wr[lane], w1=wr[lane+32], w2=wr[lane+64], w3=wr[lane+96];
        float w4=wr[lane+128], w5=wr[lane+160];
        #pragma unroll
        for (int n = 0; n < 8; n++) {
            float a = sxh[wid + 8*n][k];
            acc[n][0]=fmaf(a,w0,acc[n][0]); acc[n][1]=fmaf(a,w1,acc[n][1]);
            acc[n][2]=fmaf(a,w2,acc[n][2]); acc[n][3]=fmaf(a,w3,acc[n][3]);
            accx[n][0]=fmaf(a,w4,accx[n][0]); accx[n][1]=fmaf(a,w5,accx[n][1]);
        }
    }
    #pragma unroll 4
    for (int k = 0; k < 64; k++) {           // h @ Wh
        const float* wr = Wh + (long)k * 192;
        float w0=wr[lane], w1=wr[lane+32], w2=wr[lane+64], w3=wr[lane+96];
        float w4=wr[lane+128], w5=wr[lane+160];
        #pragma unroll
        for (int n = 0; n < 8; n++) {
            float a = sxh[wid + 8*n][64 + k];
            acc[n][0]=fmaf(a,w0,acc[n][0]); acc[n][1]=fmaf(a,w1,acc[n][1]);
            acc[n][2]=fmaf(a,w2,acc[n][2]); acc[n][3]=fmaf(a,w3,acc[n][3]);
            acch[n][0]=fmaf(a,w4,acch[n][0]); acch[n][1]=fmaf(a,w5,acch[n][1]);
        }
    }
    __syncthreads();   // all GEMM smem reads done before we overwrite x-region

    // --- elementwise GRU; new h -> sxh[.][0..63] and g_h ---
    #pragma unroll
    for (int n = 0; n < 8; n++) {
        int r = wid + 8*n;
        int node = n0 + r;
        #pragma unroll
        for (int j = 0; j < 2; j++) {
            int c = lane + 32*j;
            float z  = sigmoidf(acc[n][j]);
            float rr = sigmoidf(acc[n][2 + j]);
            float hc = tanhf(accx[n][j] + rr * acch[n][j]);
            float hold = sxh[r][64 + c];
            float hnew = z * hold + (1.f - z) * hc;
            sxh[r][c] = hnew;
            if (node < N_NODES) g_h[(long)node * HDIM + c] = hnew;
        }
    }
    __syncthreads();

    if (do_proj) {
        // --- stage C: P = h_new @ [W1a | W1b] ---
        const int j0 = lane * 8;
        const float* Wbase = (j0 < 128) ? (W1 + j0) : (W1 + 64 * MHID + (j0 - 128));
        float p[8][8];
        #pragma unroll
        for (int n = 0; n < 8; n++)
            #pragma unroll
            for (int j = 0; j < 8; j++) p[n][j] = 0.f;

        #pragma unroll 2
        for (int k = 0; k < 64; k++) {
            const float4* wp = reinterpret_cast<const float4*>(Wbase + (long)k * MHID);
            float4 wA = wp[0], wB = wp[1];
            #pragma unroll
            for (int n = 0; n < 8; n++) {
                float a = sxh[wid + 8*n][k];
                p[n][0]=fmaf(a,wA.x,p[n][0]); p[n][1]=fmaf(a,wA.y,p[n][1]);
                p[n][2]=fmaf(a,wA.z,p[n][2]); p[n][3]=fmaf(a,wA.w,p[n][3]);
                p[n][4]=fmaf(a,wB.x,p[n][4]); p[n][5]=fmaf(a,wB.y,p[n][5]);
                p[n][6]=fmaf(a,wB.z,p[n][6]); p[n][7]=fmaf(a,wB.w,p[n][7]);
            }
        }
        #pragma unroll
        for (int n = 0; n < 8; n++) {
            int node = n0 + wid + 8*n;
            if (node < N_NODES) {
                float4* op = reinterpret_cast<float4*>(g_P + (long)node * 256 + j0);
                op[0] = make_float4(p[n][0], p[n][1], p[n][2], p[n][3]);
                op[1] = make_float4(p[n][4], p[n][5], p[n][6], p[n][7]);
            }
        }
    } else {
        // --- stage R: out = relu(h_new @ Wr1 + br1) @ Wr2 + br2 ---
        float racc[8][4];
        #pragma unroll
        for (int n = 0; n < 8; n++)
            #pragma unroll
            for (int j = 0; j < 4; j++) racc[n][j] = 0.f;

        #pragma unroll 4
        for (int k = 0; k < 64; k++) {
            float w0 = Wr1[(long)k * RHID + lane];
            float w1 = Wr1[(long)k * RHID + lane + 32];
            float w2 = Wr1[(long)k * RHID + lane + 64];
            float w3 = Wr1[(long)k * RHID + lane + 96];
            #pragma unroll
            for (int n = 0; n < 8; n++) {
                float a = sxh[wid + 8*n][k];
                racc[n][0]=fmaf(a,w0,racc[n][0]); racc[n][1]=fmaf(a,w1,racc[n][1]);
                racc[n][2]=fmaf(a,w2,racc[n][2]); racc[n][3]=fmaf(a,w3,racc[n][3]);
            }
        }
        float bb[4], w2v[4];
        #pragma unroll
        for (int j = 0; j < 4; j++) {
            bb[j]  = br1[lane + 32*j];
            w2v[j] = Wr2[lane + 32*j];
        }
        float part[8];
        #pragma unroll
        for (int n = 0; n < 8; n++) {
            float s = 0.f;
            #pragma unroll
            for (int j = 0; j < 4; j++)
                s = fmaf(fmaxf(racc[n][j] + bb[j], 0.f), w2v[j], s);
            part[n] = s;
        }
        #pragma unroll
        for (int off = 16; off; off >>= 1)
            #pragma unroll
            for (int n = 0; n < 8; n++)
                part[n] += __shfl_xor_sync(0xffffffffu, part[n], off);
        if (lane == 0) {
            float bo = br2[0];
            #pragma unroll
            for (int n = 0; n < 8; n++) {
                int node = n0 + wid + 8*n;
                if (node < N_NODES) out[node] = part[n] + bo;
            }
        }
    }
}

extern "C" void kernel_launch(void* const* d_in, const int* in_sizes, int n_in,
                              void* d_out, int out_size) {
    const float* nf  = (const float*)d_in[0];
    const float* ef  = (const float*)d_in[1];
    const int*   src = (const int*)  d_in[2];
    const int*   dst = (const int*)  d_in[3];
    const float* W1  = (const float*)d_in[4];
    const float* b1  = (const float*)d_in[5];
    const float* W2  = (const float*)d_in[6];
    const float* b2  = (const float*)d_in[7];
    const float* Wx  = (const float*)d_in[8];
    const float* Wh  = (const float*)d_in[9];
    const float* bg  = (const float*)d_in[10];
    const float* Wr1 = (const float*)d_in[11];
    const float* br1 = (const float*)d_in[12];
    const float* Wr2 = (const float*)d_in[13];
    const float* br2 = (const float*)d_in[14];
    float* out = (float*)d_out;

    const int nb_nh = (N_NODES * HDIM + 255) / 256;
    const int nproj = (N_NODES + PB - 1) / PB;     // 782
    const int ngru  = (N_NODES + GB - 1) / GB;     // 782

    init_kernel<<<nb_nh, 256>>>(nf);
    proj_kernel<<<nproj, 256>>>(W1);
    // t = 0
    msg_kernel<<<N_EDGES / TE, 256>>>(ef, src, dst, W1, b1, W2, b2);
    gru_fused_kernel<<<ngru, 256>>>(Wx, Wh, bg, W1, Wr1, br1, Wr2, br2, out, 1);
    // t = 1 (readout fused)
    msg_kernel<<<N_EDGES / TE, 256>>>(ef, src, dst, W1, b1, W2, b2);
    gru_fused_kernel<<<ngru, 256>>>(Wx, Wh, bg, W1, Wr1, br1, Wr2, br2, out, 0);
}